// round 1
// baseline (speedup 1.0000x reference)
#include <cuda_runtime.h>

#define MAX_NODES 100000
#define F 128

// Scratch (allocation-free rule: __device__ globals)
__device__ __align__(16) float g_agg1[(size_t)MAX_NODES * F];   // 51.2 MB
__device__ __align__(16) float g_t2[MAX_NODES * 2];
__device__ __align__(16) float g_agg2[MAX_NODES * 2];
__device__ float g_ninv_out[MAX_NODES];   // holds deg_out, then deg_out^-0.5
__device__ float g_ninv_in[MAX_NODES];    // holds deg_in,  then deg_in^-0.5

// ---------------------------------------------------------------------------
// Zero scratch: agg1 (as float4), agg2, degree accumulators
__global__ void k_zero(int n_nodes) {
    int i = blockIdx.x * blockDim.x + threadIdx.x;
    int stride = gridDim.x * blockDim.x;
    int n4 = n_nodes * (F / 4);
    float4 z = make_float4(0.f, 0.f, 0.f, 0.f);
    for (int j = i; j < n4; j += stride) ((float4*)g_agg1)[j] = z;
    if (i < n_nodes) {
        g_ninv_out[i] = 0.f;
        g_ninv_in[i]  = 0.f;
        ((float2*)g_agg2)[i] = make_float2(0.f, 0.f);
    }
}

// ---------------------------------------------------------------------------
// Degree accumulation: one thread per edge
__global__ void k_deg(const int* __restrict__ src, const int* __restrict__ dst,
                      int n_edges) {
    int e = blockIdx.x * blockDim.x + threadIdx.x;
    if (e >= n_edges) return;
    atomicAdd(&g_ninv_out[src[e]], 1.f);
    atomicAdd(&g_ninv_in[dst[e]], 1.f);
}

// deg -> deg^-0.5 (0 for zero-degree)
__global__ void k_ninv(int n_nodes) {
    int i = blockIdx.x * blockDim.x + threadIdx.x;
    if (i >= n_nodes) return;
    float dof = g_ninv_out[i];
    float din = g_ninv_in[i];
    g_ninv_out[i] = dof > 0.f ? rsqrtf(dof) : 0.f;
    g_ninv_in[i]  = din > 0.f ? rsqrtf(din) : 0.f;
}

// ---------------------------------------------------------------------------
// Layer-1 edge aggregation: one warp per edge.
// agg1[dst] += in_feat[src] * ninv_out[src]   (128 f32 = 32 lanes x float4)
__global__ void k_edge1(const float* __restrict__ x,
                        const int* __restrict__ src,
                        const int* __restrict__ dst, int n_edges) {
    int e = (blockIdx.x * blockDim.x + threadIdx.x) >> 5;
    int lane = threadIdx.x & 31;
    if (e >= n_edges) return;
    int s = __ldg(src + e);
    int d = __ldg(dst + e);
    float sc = g_ninv_out[s];
    float4 v = __ldg((const float4*)x + (size_t)s * (F / 4) + lane);
    v.x *= sc; v.y *= sc; v.z *= sc; v.w *= sc;
    float4* o = (float4*)g_agg1 + (size_t)d * (F / 4) + lane;
    asm volatile("red.global.add.v4.f32 [%0], {%1, %2, %3, %4};"
                 :: "l"(o), "f"(v.x), "f"(v.y), "f"(v.z), "f"(v.w) : "memory");
}

// ---------------------------------------------------------------------------
// Fused: h = relu(agg1 @ W1 * ninv_in + b1); t2 = (h * ninv_out) @ W2
// Block = 128 threads, 16 rows per block, W1 staged in smem in two K-halves.
// Thread (cg = tid&31, rg = tid>>5) computes 4 rows x 4 cols.
__global__ void __launch_bounds__(128)
k_gemm_fused(const float* __restrict__ W1, const float* __restrict__ b1,
             const float* __restrict__ W2, int n_nodes) {
    __shared__ float sW[64 * F];     // 32 KB: W1[k_half][c]
    __shared__ float sX[16][64];     // 4 KB: agg1 rows, K-half

    int tid = threadIdx.x;
    int cg = tid & 31;        // column group: cols 4*cg .. 4*cg+3
    int rg = tid >> 5;        // row group: rows 4*rg .. 4*rg+3 (warp-uniform)
    int row0 = blockIdx.x * 16;

    float acc[4][4];
#pragma unroll
    for (int i = 0; i < 4; i++)
#pragma unroll
        for (int c = 0; c < 4; c++) acc[i][c] = 0.f;

    for (int half = 0; half < 2; half++) {
        // Stage W1 rows [64*half, 64*half+64) : 8192 floats = 2048 float4
        const float4* Wsrc = (const float4*)(W1 + half * 64 * F);
        for (int j = tid; j < 2048; j += 128)
            ((float4*)sW)[j] = __ldg(Wsrc + j);
        // Stage 16 rows of agg1, K-half: 1024 floats = 256 float4
        for (int j = tid; j < 256; j += 128) {
            int r = j >> 4, c4 = j & 15;
            int row = row0 + r;
            if (row < n_nodes)
                ((float4*)&sX[r][0])[c4] =
                    *((const float4*)(g_agg1 + (size_t)row * F + half * 64) + c4);
        }
        __syncthreads();
#pragma unroll
        for (int k = 0; k < 64; k++) {
            float4 w = ((const float4*)(sW + k * F))[cg];
#pragma unroll
            for (int i = 0; i < 4; i++) {
                float xv = sX[rg * 4 + i][k];   // warp-broadcast
                acc[i][0] = fmaf(xv, w.x, acc[i][0]);
                acc[i][1] = fmaf(xv, w.y, acc[i][1]);
                acc[i][2] = fmaf(xv, w.z, acc[i][2]);
                acc[i][3] = fmaf(xv, w.w, acc[i][3]);
            }
        }
        __syncthreads();
    }

    // Epilogue: per-row relu + norms, project to 2 cols of W2, warp-reduce.
    float w2a[4], w2b[4], bb[4];
#pragma unroll
    for (int c = 0; c < 4; c++) {
        int col = cg * 4 + c;
        bb[c]  = __ldg(b1 + col);
        w2a[c] = __ldg(W2 + col * 2);
        w2b[c] = __ldg(W2 + col * 2 + 1);
    }
#pragma unroll
    for (int i = 0; i < 4; i++) {
        int row = row0 + rg * 4 + i;
        bool valid = row < n_nodes;
        int rr = valid ? row : 0;
        float ni = g_ninv_in[rr];
        float no = g_ninv_out[rr];
        float p0 = 0.f, p1 = 0.f;
#pragma unroll
        for (int c = 0; c < 4; c++) {
            float h = fmaf(acc[i][c], ni, bb[c]);
            h = fmaxf(h, 0.f) * no;
            p0 = fmaf(h, w2a[c], p0);
            p1 = fmaf(h, w2b[c], p1);
        }
#pragma unroll
        for (int off = 16; off; off >>= 1) {
            p0 += __shfl_xor_sync(0xffffffffu, p0, off);
            p1 += __shfl_xor_sync(0xffffffffu, p1, off);
        }
        if (cg == 0 && valid) {
            g_t2[row * 2]     = p0;
            g_t2[row * 2 + 1] = p1;
        }
    }
}

// ---------------------------------------------------------------------------
// Layer-2 edge aggregation: one thread per edge, 2 floats each.
__global__ void k_edge2(const int* __restrict__ src, const int* __restrict__ dst,
                        int n_edges) {
    int e = blockIdx.x * blockDim.x + threadIdx.x;
    if (e >= n_edges) return;
    int s = __ldg(src + e);
    int d = __ldg(dst + e);
    float2 v = ((const float2*)g_t2)[s];
    float2* o = (float2*)g_agg2 + d;
    asm volatile("red.global.add.v2.f32 [%0], {%1, %2};"
                 :: "l"(o), "f"(v.x), "f"(v.y) : "memory");
}

// Final epilogue: out = agg2 * ninv_in + b2
__global__ void k_out(const float* __restrict__ b2, float* __restrict__ out,
                      int n_nodes) {
    int i = blockIdx.x * blockDim.x + threadIdx.x;
    if (i >= n_nodes) return;
    float ni = g_ninv_in[i];
    float2 a = ((float2*)g_agg2)[i];
    float2 o;
    o.x = fmaf(a.x, ni, __ldg(b2));
    o.y = fmaf(a.y, ni, __ldg(b2 + 1));
    ((float2*)out)[i] = o;
}

// ---------------------------------------------------------------------------
extern "C" void kernel_launch(void* const* d_in, const int* in_sizes, int n_in,
                              void* d_out, int out_size) {
    const float* x  = (const float*)d_in[0];
    const float* W1 = (const float*)d_in[1];
    const float* b1 = (const float*)d_in[2];
    const float* W2 = (const float*)d_in[3];
    const float* b2 = (const float*)d_in[4];
    const int* src  = (const int*)d_in[5];
    const int* dst  = (const int*)d_in[6];
    int n_nodes = in_sizes[0] / F;
    int n_edges = in_sizes[5];

    int nb;
    nb = (n_nodes * (F / 4) + 255) / 256;
    k_zero<<<nb, 256>>>(n_nodes);

    nb = (n_edges + 255) / 256;
    k_deg<<<nb, 256>>>(src, dst, n_edges);

    nb = (n_nodes + 255) / 256;
    k_ninv<<<nb, 256>>>(n_nodes);

    long t1 = (long)n_edges * 32;               // warp per edge
    nb = (int)((t1 + 255) / 256);
    k_edge1<<<nb, 256>>>(x, src, dst, n_edges);

    nb = (n_nodes + 15) / 16;
    k_gemm_fused<<<nb, 128>>>(W1, b1, W2, n_nodes);

    nb = (n_edges + 255) / 256;
    k_edge2<<<nb, 256>>>(src, dst, n_edges);

    nb = (n_nodes + 255) / 256;
    k_out<<<nb, 256>>>(b2, (float*)d_out, n_nodes);
}